// round 14
// baseline (speedup 1.0000x reference)
#include <cuda_runtime.h>
#include <cuda_bf16.h>
#include <math.h>
#include <cstdint>

// ---------------------------------------------------------------------------
// SelectiveStateSpace: B=8, S=2048, D_MODEL=1024, N=64
//   wconv     : W fp32 -> bf16 hi/lo split (+ clears lookback flags)
//   proj_mma  : ldmatrix + mma.sync bf16 3-term GEMM  D = X @ Wcat^T
//   scan_fused: decoupled-lookback chunked scan (pass A -> publish -> lookback
//               -> pass B), whole chunk resident in smem. R8 lane layout.
// R11: fixes R10's staging OOB (u stage 8 f4/thr not 32; C prefetch 1/tile).
// ---------------------------------------------------------------------------

#define BQ   8
#define SQ   2048
#define DM   1024
#define NS   64
#define ROWS (BQ * SQ)        // 16384
#define RQ   (BQ * NS)        // 512
#define GQ   16               // chunks per row
#define LQ   (SQ / GQ)        // 128 steps per chunk

#define MT   128
#define NTOT 192
#define KC   32
#define NKC  (DM / KC)        // 32

#define LOG2E 1.4426950408889634f

// proj smem geometry (bytes): rows padded to 80B for ldmatrix
#define ROWB   80
#define A_TERM (MT * ROWB)
#define B_TERM (NTOT * ROWB)
#define A_OFF  0
#define B_OFF  (2 * A_TERM)
#define STG_SZ (2 * A_TERM + 2 * B_TERM)
#define SMEM_MMA (2 * STG_SZ)

// fused-scan smem (floats): su[128][64] | sc[128][64] | sd[128][32] | ys[128][32]
#define SU_OFF 0
#define SC_OFF (128 * 64)
#define SD_OFF (2 * 128 * 64)
#define YS_OFF (2 * 128 * 64 + 128 * 32)
#define SMEM_SCAN ((2 * 128 * 64 + 2 * 128 * 32) * 4)   // 98304 B

// scratch (device globals; no allocation allowed)
__device__ float g_delta[ROWS * NS];
__device__ float g_u[ROWS * NS];
__device__ float g_c[ROWS * NS];
__device__ float g_hend[RQ * GQ * NS];
__device__ float g_dsum[RQ * GQ];
__device__ int   g_flag[BQ * GQ * 2];
__device__ uint4 g_Whi4[NTOT * DM / 8];
__device__ uint4 g_Wlo4[NTOT * DM / 8];

// ------------------------------ helpers -------------------------------------
__device__ __forceinline__ uint32_t smem_u32(const void* p) {
    uint32_t a;
    asm("{ .reg .u64 t; cvta.to.shared.u64 t, %1; cvt.u32.u64 %0, t; }"
        : "=r"(a) : "l"(p));
    return a;
}
__device__ __forceinline__ float ex2(float x) {
    float r;
    asm("ex2.approx.ftz.f32 %0, %1;" : "=f"(r) : "f"(x));
    return r;
}
__device__ __forceinline__ float softplus_f(float v) {
    return (v > 20.0f) ? v : log1pf(expf(v));
}
__device__ __forceinline__ uint32_t hipack(float a, float b) {
    __nv_bfloat162 h;
    h.x = __float2bfloat16(a);
    h.y = __float2bfloat16(b);
    return *(uint32_t*)&h;
}
__device__ __forceinline__ uint32_t lopack(float a, float b) {
    __nv_bfloat16 ha = __float2bfloat16(a), hb = __float2bfloat16(b);
    __nv_bfloat162 h;
    h.x = __float2bfloat16(a - __bfloat162float(ha));
    h.y = __float2bfloat16(b - __bfloat162float(hb));
    return *(uint32_t*)&h;
}
__device__ __forceinline__ void ldsm4(uint32_t* r, uint32_t addr) {
    asm volatile("ldmatrix.sync.aligned.m8n8.x4.shared.b16 {%0,%1,%2,%3}, [%4];"
                 : "=r"(r[0]), "=r"(r[1]), "=r"(r[2]), "=r"(r[3]) : "r"(addr));
}
__device__ __forceinline__ void mma16816(float* c, const uint32_t* a, const uint32_t* b) {
    asm volatile(
        "mma.sync.aligned.m16n8k16.row.col.f32.bf16.bf16.f32 "
        "{%0,%1,%2,%3}, {%4,%5,%6,%7}, {%8,%9}, {%0,%1,%2,%3};"
        : "+f"(c[0]), "+f"(c[1]), "+f"(c[2]), "+f"(c[3])
        : "r"(a[0]), "r"(a[1]), "r"(a[2]), "r"(a[3]), "r"(b[0]), "r"(b[1]));
}

// ------------------------------ W conversion (+flag clear) ------------------
__global__ void __launch_bounds__(256, 1)
wconv_kernel(const float* __restrict__ Wd, const float* __restrict__ Wb,
             const float* __restrict__ Wc) {
    if (blockIdx.x == 0 && threadIdx.x < BQ * GQ * 2) g_flag[threadIdx.x] = 0;
    int gi = blockIdx.x * 256 + threadIdx.x;
    int row = gi >> 7;
    int k8  = (gi & 127) * 8;
    const float* src = (row < 64) ? (Wd + (size_t)row * DM)
                    : (row < 128) ? (Wb + (size_t)(row - 64) * DM)
                                  : (Wc + (size_t)(row - 128) * DM);
    float f[8];
    *(float4*)&f[0] = *(const float4*)(src + k8);
    *(float4*)&f[4] = *(const float4*)(src + k8 + 4);
    uint4 hi, lo;
    hi.x = hipack(f[0], f[1]); hi.y = hipack(f[2], f[3]);
    hi.z = hipack(f[4], f[5]); hi.w = hipack(f[6], f[7]);
    lo.x = lopack(f[0], f[1]); lo.y = lopack(f[2], f[3]);
    lo.z = lopack(f[4], f[5]); lo.w = lopack(f[6], f[7]);
    g_Whi4[gi] = hi;
    g_Wlo4[gi] = lo;
}

// ------------------------------ proj (mma.sync) -----------------------------
__global__ void __launch_bounds__(256, 1)
proj_mma_kernel(const float* __restrict__ x,
                const float* __restrict__ bd, const float* __restrict__ bb,
                const float* __restrict__ bc) {
    extern __shared__ char smem[];
    const uint32_t sb = smem_u32(smem);
    const int tid    = threadIdx.x;
    const int lane   = tid & 31;
    const int warp   = tid >> 5;
    const int warp_m = warp >> 2;
    const int warp_n = warp & 3;
    const int m0     = blockIdx.x * MT;

    float acc[4][6][4];
#pragma unroll
    for (int fm = 0; fm < 4; fm++)
#pragma unroll
        for (int fn = 0; fn < 6; fn++)
#pragma unroll
            for (int e = 0; e < 4; e++) acc[fm][fn][e] = 0.0f;

    float4 xr[4];
    uint4  wh[3], wl[3];
    const int xrow = tid >> 1;
    const int xco  = (tid & 1) * 16;

#define LDCHUNK(c)                                                              \
    do {                                                                        \
        const float* xp = x + (size_t)(m0 + xrow) * DM + (c) * KC + xco;        \
        xr[0] = *(const float4*)(xp + 0);                                       \
        xr[1] = *(const float4*)(xp + 4);                                       \
        xr[2] = *(const float4*)(xp + 8);                                       \
        xr[3] = *(const float4*)(xp + 12);                                      \
        _Pragma("unroll")                                                       \
        for (int q = 0; q < 3; q++) {                                           \
            int idx = tid + q * 256;                                            \
            int wrow = idx >> 2, wch = idx & 3;                                 \
            int u4 = wrow * 128 + (c) * 4 + wch;                                \
            wh[q] = g_Whi4[u4];                                                 \
            wl[q] = g_Wlo4[u4];                                                 \
        }                                                                       \
    } while (0)

#define STCHUNK(buf)                                                            \
    do {                                                                        \
        char* bs = smem + (buf) * STG_SZ;                                       \
        uint4 h0 = make_uint4(hipack(xr[0].x, xr[0].y), hipack(xr[0].z, xr[0].w),\
                              hipack(xr[1].x, xr[1].y), hipack(xr[1].z, xr[1].w));\
        uint4 h1 = make_uint4(hipack(xr[2].x, xr[2].y), hipack(xr[2].z, xr[2].w),\
                              hipack(xr[3].x, xr[3].y), hipack(xr[3].z, xr[3].w));\
        uint4 l0 = make_uint4(lopack(xr[0].x, xr[0].y), lopack(xr[0].z, xr[0].w),\
                              lopack(xr[1].x, xr[1].y), lopack(xr[1].z, xr[1].w));\
        uint4 l1 = make_uint4(lopack(xr[2].x, xr[2].y), lopack(xr[2].z, xr[2].w),\
                              lopack(xr[3].x, xr[3].y), lopack(xr[3].z, xr[3].w));\
        int ach = (tid & 1) * 2;                                                \
        *(uint4*)(bs + A_OFF + xrow * ROWB + ach * 16)        = h0;             \
        *(uint4*)(bs + A_OFF + xrow * ROWB + (ach + 1) * 16)  = h1;             \
        *(uint4*)(bs + A_OFF + A_TERM + xrow * ROWB + ach * 16)       = l0;     \
        *(uint4*)(bs + A_OFF + A_TERM + xrow * ROWB + (ach + 1) * 16) = l1;     \
        _Pragma("unroll")                                                       \
        for (int q = 0; q < 3; q++) {                                           \
            int idx = tid + q * 256;                                            \
            int wrow = idx >> 2, wch = idx & 3;                                 \
            *(uint4*)(bs + B_OFF + wrow * ROWB + wch * 16) = wh[q];             \
            *(uint4*)(bs + B_OFF + B_TERM + wrow * ROWB + wch * 16) = wl[q];    \
        }                                                                       \
    } while (0)

    LDCHUNK(0);
    STCHUNK(0);
    __syncthreads();
    LDCHUNK(1);

    for (int c = 0; c < NKC; c++) {
        const uint32_t bs = sb + (uint32_t)(c & 1) * STG_SZ;
#pragma unroll
        for (int ks = 0; ks < 2; ks++) {
            const int arow_l = (lane & 15);
            const int achk   = ks * 2 + (lane >> 4);
            const int brow_l = (lane & 7) + ((lane >> 4) << 3);
            const int bchk   = ks * 2 + ((lane >> 3) & 1);
#pragma unroll
            for (int term = 0; term < 3; term++) {
                const uint32_t aoff = bs + A_OFF + ((term == 2) ? A_TERM : 0);
                const uint32_t boff = bs + B_OFF + ((term == 1) ? B_TERM : 0);
                uint32_t bfr[6][2];
#pragma unroll
                for (int bn = 0; bn < 3; bn++) {
                    uint32_t r[4];
                    int brow = warp_n * 48 + bn * 16 + brow_l;
                    ldsm4(r, boff + brow * ROWB + bchk * 16);
                    bfr[2 * bn][0] = r[0]; bfr[2 * bn][1] = r[1];
                    bfr[2 * bn + 1][0] = r[2]; bfr[2 * bn + 1][1] = r[3];
                }
#pragma unroll
                for (int fm = 0; fm < 4; fm++) {
                    uint32_t a[4];
                    int arow = warp_m * 64 + fm * 16 + arow_l;
                    ldsm4(a, aoff + arow * ROWB + achk * 16);
#pragma unroll
                    for (int fn = 0; fn < 6; fn++)
                        mma16816(acc[fm][fn], a, bfr[fn]);
                }
            }
        }
        if (c + 1 < NKC) {
            STCHUNK((c + 1) & 1);
            __syncthreads();
            if (c + 2 < NKC) LDCHUNK(c + 2);
        }
    }

    const int g = lane >> 2;
    const int t = lane & 3;
#pragma unroll
    for (int fn = 0; fn < 6; fn++) {
        const int nblk = warp_n * 48 + fn * 8;
        const int n    = nblk + 2 * t;
#pragma unroll
        for (int fm = 0; fm < 4; fm++) {
#pragma unroll
            for (int half = 0; half < 2; half++) {
                const int m = m0 + warp_m * 64 + fm * 16 + g + half * 8;
                float v0 = acc[fm][fn][2 * half + 0];
                float v1 = acc[fm][fn][2 * half + 1];
                if (nblk < 64) {
                    v0 = softplus_f(v0 + bd[n]);
                    v1 = softplus_f(v1 + bd[n + 1]);
                    *(float2*)&g_delta[(size_t)m * NS + n] = make_float2(v0, v1);
                } else if (nblk < 128) {
                    const int j = n - 64;
                    float2 xv = *(const float2*)&x[(size_t)m * DM + j];
                    v0 = (v0 + bb[j]) * xv.x;
                    v1 = (v1 + bb[j + 1]) * xv.y;
                    *(float2*)&g_u[(size_t)m * NS + j] = make_float2(v0, v1);
                } else {
                    const int j = n - 128;
                    v0 += bc[j];
                    v1 += bc[j + 1];
                    *(float2*)&g_c[(size_t)m * NS + j] = make_float2(v0, v1);
                }
            }
        }
    }
}

// --------------------------- fused decoupled scan ----------------------------
// grid 256 (b[8] x chunk[16] x half[2]); 256 thr = 8 warps x 4 i-rows;
// lane: isub = l>>3, g = l&7 owns j in {4g..4g+3, 32+4g..32+4g+3}.
__global__ void __launch_bounds__(256, 1)
scan_fused_kernel(const float* __restrict__ A_log, float* __restrict__ out) {
    extern __shared__ float sf[];
    float* su = sf + SU_OFF;   // [128][64]
    float* sc = sf + SC_OFF;   // [128][64]
    float* sd = sf + SD_OFF;   // [128][32] (this half's i rows)
    float* ys = sf + YS_OFF;   // [128][32]

    const int tid = threadIdx.x;
    const int w   = tid >> 5;
    const int l   = tid & 31;
    const int isub = l >> 3;
    const int g    = l & 7;
    const int bx  = blockIdx.x;
    const int b     = bx >> 5;
    const int chunk = (bx >> 1) & 15;
    const int half  = bx & 1;
    const int iblk  = w * 4 + isub;          // 0..31
    const int i     = half * 32 + iblk;
    const int row   = b * NS + i;
    const int t0    = chunk * LQ;

    float a[8];
    *(float4*)&a[0] = *(const float4*)&A_log[i * NS + 4 * g];
    *(float4*)&a[4] = *(const float4*)&A_log[i * NS + 32 + 4 * g];
#pragma unroll
    for (int k = 0; k < 8; k++) a[k] *= LOG2E;

    const float* ubase = g_u + ((size_t)(b * SQ + t0)) * NS;
    const float* cbase = g_c + ((size_t)(b * SQ + t0)) * NS;
    const float* dbase = g_delta + ((size_t)(b * SQ + t0)) * NS + half * 32;

    // ---- stage u (8 f4/thr = 2048 f4 total) and delta-half (4 f4/thr) ----
#pragma unroll
    for (int k = 0; k < 8; k++) {
        int idx = tid + k * 256;               // 0..2047
        int r = idx >> 4, c4 = (idx & 15) << 2;
        *(float4*)&su[r * 64 + c4] = *(const float4*)(ubase + (size_t)r * NS + c4);
    }
#pragma unroll
    for (int k = 0; k < 4; k++) {
        int idx = tid + k * 256;               // 0..1023
        int r = idx >> 3, c4 = (idx & 7) << 2;
        *(float4*)&sd[r * 32 + c4] = *(const float4*)(dbase + (size_t)r * NS + c4);
    }
    __syncthreads();

    // ---- pass A: local scan (h=0) -> h_end, dsum; prefetch C under it ----
    // One tile = 16 steps = 256 f4 of C = exactly 1 f4/thread.
    float h[8] = {0.f, 0.f, 0.f, 0.f, 0.f, 0.f, 0.f, 0.f};
    float dsum = 0.0f;
#pragma unroll 1
    for (int tile = 0; tile < 8; tile++) {
        float4 cpre;
        {
            int idx = tid + tile * 256;        // 0..2047
            int r = idx >> 4, c4 = (idx & 15) << 2;
            cpre = *(const float4*)(cbase + (size_t)r * NS + c4);
        }
#pragma unroll
        for (int s0 = 0; s0 < 16; s0++) {
            const int s = tile * 16 + s0;
            float d = sd[s * 32 + iblk];
            float4 ua = *(const float4*)&su[s * 64 + 4 * g];
            float4 ub = *(const float4*)&su[s * 64 + 32 + 4 * g];
            dsum += d;
            h[0] = ex2(a[0] * d) * h[0] + ua.x;
            h[1] = ex2(a[1] * d) * h[1] + ua.y;
            h[2] = ex2(a[2] * d) * h[2] + ua.z;
            h[3] = ex2(a[3] * d) * h[3] + ua.w;
            h[4] = ex2(a[4] * d) * h[4] + ub.x;
            h[5] = ex2(a[5] * d) * h[5] + ub.y;
            h[6] = ex2(a[6] * d) * h[6] + ub.z;
            h[7] = ex2(a[7] * d) * h[7] + ub.w;
        }
        {
            int idx = tid + tile * 256;
            int r = idx >> 4, c4 = (idx & 15) << 2;
            *(float4*)&sc[r * 64 + c4] = cpre;
        }
    }

    // ---- publish h_end + dsum, release flag ----
    {
        float* he = g_hend + ((size_t)row * GQ + chunk) * NS;
        *(float4*)(he + 4 * g)      = make_float4(h[0], h[1], h[2], h[3]);
        *(float4*)(he + 32 + 4 * g) = make_float4(h[4], h[5], h[6], h[7]);
        if (g == 0) g_dsum[row * GQ + chunk] = dsum;
    }
    __threadfence();
    __syncthreads();           // also makes sc stores visible block-wide
    if (tid == 0) ((volatile int*)g_flag)[bx] = 1;

    // ---- lookback: h_start = sum_{p<chunk} exp2(a * S_p) * h_end[p] ----
#pragma unroll
    for (int k = 0; k < 8; k++) h[k] = 0.0f;
    {
        float S = 0.0f;
        const float* dsp = g_dsum + row * GQ;
        const float* hep = g_hend + ((size_t)row * GQ) * NS;
        for (int p = chunk - 1; p >= 0; p--) {
            const int fidx = (b << 5) | (p << 1) | half;
            if (l == 0) {
                while (((volatile int*)g_flag)[fidx] == 0) {}
            }
            __syncwarp();
            __threadfence();   // acquire: order flag read before data reads
            float4 he0 = *(const float4*)(hep + (size_t)p * NS + 4 * g);
            float4 he1 = *(const float4*)(hep + (size_t)p * NS + 32 + 4 * g);
            h[0] += ex2(a[0] * S) * he0.x;
            h[1] += ex2(a[1] * S) * he0.y;
            h[2] += ex2(a[2] * S) * he0.z;
            h[3] += ex2(a[3] * S) * he0.w;
            h[4] += ex2(a[4] * S) * he1.x;
            h[5] += ex2(a[5] * S) * he1.y;
            h[6] += ex2(a[6] * S) * he1.z;
            h[7] += ex2(a[7] * S) * he1.w;
            S += dsp[p];
        }
    }

    // ---- pass B: rescan with h_start, emit y ----
#pragma unroll 1
    for (int tile = 0; tile < 8; tile++) {
#pragma unroll
        for (int s0 = 0; s0 < 16; s0++) {
            const int s = tile * 16 + s0;
            float d = sd[s * 32 + iblk];
            float4 ua = *(const float4*)&su[s * 64 + 4 * g];
            float4 ub = *(const float4*)&su[s * 64 + 32 + 4 * g];
            float4 ca = *(const float4*)&sc[s * 64 + 4 * g];
            float4 cb = *(const float4*)&sc[s * 64 + 32 + 4 * g];
            h[0] = ex2(a[0] * d) * h[0] + ua.x;
            h[1] = ex2(a[1] * d) * h[1] + ua.y;
            h[2] = ex2(a[2] * d) * h[2] + ua.z;
            h[3] = ex2(a[3] * d) * h[3] + ua.w;
            h[4] = ex2(a[4] * d) * h[4] + ub.x;
            h[5] = ex2(a[5] * d) * h[5] + ub.y;
            h[6] = ex2(a[6] * d) * h[6] + ub.z;
            h[7] = ex2(a[7] * d) * h[7] + ub.w;
            float p = ca.x * h[0] + ca.y * h[1] + ca.z * h[2] + ca.w * h[3]
                    + cb.x * h[4] + cb.y * h[5] + cb.z * h[6] + cb.w * h[7];
            p += __shfl_xor_sync(0xffffffffu, p, 4);
            p += __shfl_xor_sync(0xffffffffu, p, 2);
            p += __shfl_xor_sync(0xffffffffu, p, 1);
            if (g == 0) ys[s * 32 + iblk] = p;
        }
    }
    __syncthreads();

    // ---- coalesced y writeout: 4 f4/thread (1024 f4 = 128x32 floats) ----
#pragma unroll
    for (int k = 0; k < 4; k++) {
        int idx = tid + k * 256;               // 0..1023
        int s = idx >> 3, c4 = (idx & 7) << 2;
        *(float4*)&out[((size_t)(b * SQ + t0 + s)) * NS + half * 32 + c4] =
            *(const float4*)&ys[s * 32 + c4];
    }
}

// --------------------------------- launch -----------------------------------
extern "C" void kernel_launch(void* const* d_in, const int* in_sizes, int n_in,
                              void* d_out, int out_size) {
    const float* x  = (const float*)d_in[0];
    const float* Wd = (const float*)d_in[7];
    const float* bd = (const float*)d_in[8];
    const float* Wb = (const float*)d_in[9];
    const float* bb = (const float*)d_in[10];
    const float* Wc = (const float*)d_in[11];
    const float* bc = (const float*)d_in[12];
    const float* A  = (const float*)d_in[13];
    float* out = (float*)d_out;

    cudaFuncSetAttribute(proj_mma_kernel,
                         cudaFuncAttributeMaxDynamicSharedMemorySize, SMEM_MMA);
    cudaFuncSetAttribute(scan_fused_kernel,
                         cudaFuncAttributeMaxDynamicSharedMemorySize, SMEM_SCAN);

    wconv_kernel<<<NTOT * DM / 8 / 256, 256>>>(Wd, Wb, Wc);
    proj_mma_kernel<<<ROWS / MT, 256, SMEM_MMA>>>(x, bd, bb, bc);
    scan_fused_kernel<<<BQ * GQ * 2, 256, SMEM_SCAN>>>(A, out);
}

// round 15
// speedup vs baseline: 1.1325x; 1.1325x over previous
#include <cuda_runtime.h>
#include <cuda_bf16.h>
#include <math.h>
#include <cstdint>

// ---------------------------------------------------------------------------
// SelectiveStateSpace: B=8, S=2048, D_MODEL=1024, N=64
//   wconv    : W[192,1024] fp32 -> bf16 hi/lo split
//   proj_mma : ldmatrix + mma.sync bf16 3-term GEMM  D = X @ Wcat^T
//   scan1    : FINE chunks (F=32, 64 steps) local scan -> h_end, sum(delta)
//   scan3    : coarse chunks (GQ=16, 128 steps); lookback over fine entries
// R15 = R8 base + fine-grained scan1 for occupancy (512 blocks, 4/SM).
// ---------------------------------------------------------------------------

#define BQ   8
#define SQ   2048
#define DM   1024
#define NS   64
#define ROWS (BQ * SQ)        // 16384
#define RQ   (BQ * NS)        // 512
#define GQ   16               // coarse chunks per row (scan3)
#define LQ   (SQ / GQ)        // 128 steps per coarse chunk
#define GQF  32               // fine chunks per row (scan1)
#define LQF  (SQ / GQF)       // 64 steps per fine chunk
#define TS   16
#define NTIL  (LQ / TS)       // 8
#define NTILF (LQF / TS)      // 4

#define MT   128
#define NTOT 192
#define KC   32
#define NKC  (DM / KC)        // 32

#define LOG2E 1.4426950408889634f

// proj smem geometry (bytes): rows padded to 80B for ldmatrix
#define ROWB   80
#define A_TERM (MT * ROWB)
#define B_TERM (NTOT * ROWB)
#define A_OFF  0
#define B_OFF  (2 * A_TERM)
#define STG_SZ (2 * A_TERM + 2 * B_TERM)
#define SMEM_MMA (2 * STG_SZ)

// scratch (device globals; no allocation allowed)
__device__ float g_delta[ROWS * NS];
__device__ float g_u[ROWS * NS];
__device__ float g_c[ROWS * NS];
__device__ float g_hend[RQ * GQF * NS];
__device__ float g_dsum[RQ * GQF];
__device__ uint4 g_Whi4[NTOT * DM / 8];
__device__ uint4 g_Wlo4[NTOT * DM / 8];

// ------------------------------ helpers -------------------------------------
__device__ __forceinline__ uint32_t smem_u32(const void* p) {
    uint32_t a;
    asm("{ .reg .u64 t; cvta.to.shared.u64 t, %1; cvt.u32.u64 %0, t; }"
        : "=r"(a) : "l"(p));
    return a;
}
__device__ __forceinline__ float ex2(float x) {
    float r;
    asm("ex2.approx.ftz.f32 %0, %1;" : "=f"(r) : "f"(x));
    return r;
}
__device__ __forceinline__ float softplus_f(float v) {
    return (v > 20.0f) ? v : log1pf(expf(v));
}
__device__ __forceinline__ uint32_t hipack(float a, float b) {
    __nv_bfloat162 h;
    h.x = __float2bfloat16(a);
    h.y = __float2bfloat16(b);
    return *(uint32_t*)&h;
}
__device__ __forceinline__ uint32_t lopack(float a, float b) {
    __nv_bfloat16 ha = __float2bfloat16(a), hb = __float2bfloat16(b);
    __nv_bfloat162 h;
    h.x = __float2bfloat16(a - __bfloat162float(ha));
    h.y = __float2bfloat16(b - __bfloat162float(hb));
    return *(uint32_t*)&h;
}
__device__ __forceinline__ void ldsm4(uint32_t* r, uint32_t addr) {
    asm volatile("ldmatrix.sync.aligned.m8n8.x4.shared.b16 {%0,%1,%2,%3}, [%4];"
                 : "=r"(r[0]), "=r"(r[1]), "=r"(r[2]), "=r"(r[3]) : "r"(addr));
}
__device__ __forceinline__ void mma16816(float* c, const uint32_t* a, const uint32_t* b) {
    asm volatile(
        "mma.sync.aligned.m16n8k16.row.col.f32.bf16.bf16.f32 "
        "{%0,%1,%2,%3}, {%4,%5,%6,%7}, {%8,%9}, {%0,%1,%2,%3};"
        : "+f"(c[0]), "+f"(c[1]), "+f"(c[2]), "+f"(c[3])
        : "r"(a[0]), "r"(a[1]), "r"(a[2]), "r"(a[3]), "r"(b[0]), "r"(b[1]));
}

// ------------------------------ W conversion --------------------------------
__global__ void __launch_bounds__(256, 1)
wconv_kernel(const float* __restrict__ Wd, const float* __restrict__ Wb,
             const float* __restrict__ Wc) {
    int gi = blockIdx.x * 256 + threadIdx.x;
    int row = gi >> 7;
    int k8  = (gi & 127) * 8;
    const float* src = (row < 64) ? (Wd + (size_t)row * DM)
                    : (row < 128) ? (Wb + (size_t)(row - 64) * DM)
                                  : (Wc + (size_t)(row - 128) * DM);
    float f[8];
    *(float4*)&f[0] = *(const float4*)(src + k8);
    *(float4*)&f[4] = *(const float4*)(src + k8 + 4);
    uint4 hi, lo;
    hi.x = hipack(f[0], f[1]); hi.y = hipack(f[2], f[3]);
    hi.z = hipack(f[4], f[5]); hi.w = hipack(f[6], f[7]);
    lo.x = lopack(f[0], f[1]); lo.y = lopack(f[2], f[3]);
    lo.z = lopack(f[4], f[5]); lo.w = lopack(f[6], f[7]);
    g_Whi4[gi] = hi;
    g_Wlo4[gi] = lo;
}

// ------------------------------ proj (mma.sync) -----------------------------
__global__ void __launch_bounds__(256, 1)
proj_mma_kernel(const float* __restrict__ x,
                const float* __restrict__ bd, const float* __restrict__ bb,
                const float* __restrict__ bc) {
    extern __shared__ char smem[];
    const uint32_t sb = smem_u32(smem);
    const int tid    = threadIdx.x;
    const int lane   = tid & 31;
    const int warp   = tid >> 5;
    const int warp_m = warp >> 2;
    const int warp_n = warp & 3;
    const int m0     = blockIdx.x * MT;

    float acc[4][6][4];
#pragma unroll
    for (int fm = 0; fm < 4; fm++)
#pragma unroll
        for (int fn = 0; fn < 6; fn++)
#pragma unroll
            for (int e = 0; e < 4; e++) acc[fm][fn][e] = 0.0f;

    float4 xr[4];
    uint4  wh[3], wl[3];
    const int xrow = tid >> 1;
    const int xco  = (tid & 1) * 16;

#define LDCHUNK(c)                                                              \
    do {                                                                        \
        const float* xp = x + (size_t)(m0 + xrow) * DM + (c) * KC + xco;        \
        xr[0] = *(const float4*)(xp + 0);                                       \
        xr[1] = *(const float4*)(xp + 4);                                       \
        xr[2] = *(const float4*)(xp + 8);                                       \
        xr[3] = *(const float4*)(xp + 12);                                      \
        _Pragma("unroll")                                                       \
        for (int q = 0; q < 3; q++) {                                           \
            int idx = tid + q * 256;                                            \
            int wrow = idx >> 2, wch = idx & 3;                                 \
            int u4 = wrow * 128 + (c) * 4 + wch;                                \
            wh[q] = g_Whi4[u4];                                                 \
            wl[q] = g_Wlo4[u4];                                                 \
        }                                                                       \
    } while (0)

#define STCHUNK(buf)                                                            \
    do {                                                                        \
        char* bs = smem + (buf) * STG_SZ;                                       \
        uint4 h0 = make_uint4(hipack(xr[0].x, xr[0].y), hipack(xr[0].z, xr[0].w),\
                              hipack(xr[1].x, xr[1].y), hipack(xr[1].z, xr[1].w));\
        uint4 h1 = make_uint4(hipack(xr[2].x, xr[2].y), hipack(xr[2].z, xr[2].w),\
                              hipack(xr[3].x, xr[3].y), hipack(xr[3].z, xr[3].w));\
        uint4 l0 = make_uint4(lopack(xr[0].x, xr[0].y), lopack(xr[0].z, xr[0].w),\
                              lopack(xr[1].x, xr[1].y), lopack(xr[1].z, xr[1].w));\
        uint4 l1 = make_uint4(lopack(xr[2].x, xr[2].y), lopack(xr[2].z, xr[2].w),\
                              lopack(xr[3].x, xr[3].y), lopack(xr[3].z, xr[3].w));\
        int ach = (tid & 1) * 2;                                                \
        *(uint4*)(bs + A_OFF + xrow * ROWB + ach * 16)        = h0;             \
        *(uint4*)(bs + A_OFF + xrow * ROWB + (ach + 1) * 16)  = h1;             \
        *(uint4*)(bs + A_OFF + A_TERM + xrow * ROWB + ach * 16)       = l0;     \
        *(uint4*)(bs + A_OFF + A_TERM + xrow * ROWB + (ach + 1) * 16) = l1;     \
        _Pragma("unroll")                                                       \
        for (int q = 0; q < 3; q++) {                                           \
            int idx = tid + q * 256;                                            \
            int wrow = idx >> 2, wch = idx & 3;                                 \
            *(uint4*)(bs + B_OFF + wrow * ROWB + wch * 16) = wh[q];             \
            *(uint4*)(bs + B_OFF + B_TERM + wrow * ROWB + wch * 16) = wl[q];    \
        }                                                                       \
    } while (0)

    LDCHUNK(0);
    STCHUNK(0);
    __syncthreads();
    LDCHUNK(1);

    for (int c = 0; c < NKC; c++) {
        const uint32_t bs = sb + (uint32_t)(c & 1) * STG_SZ;
#pragma unroll
        for (int ks = 0; ks < 2; ks++) {
            const int arow_l = (lane & 15);
            const int achk   = ks * 2 + (lane >> 4);
            const int brow_l = (lane & 7) + ((lane >> 4) << 3);
            const int bchk   = ks * 2 + ((lane >> 3) & 1);
#pragma unroll
            for (int term = 0; term < 3; term++) {
                const uint32_t aoff = bs + A_OFF + ((term == 2) ? A_TERM : 0);
                const uint32_t boff = bs + B_OFF + ((term == 1) ? B_TERM : 0);
                uint32_t bfr[6][2];
#pragma unroll
                for (int bn = 0; bn < 3; bn++) {
                    uint32_t r[4];
                    int brow = warp_n * 48 + bn * 16 + brow_l;
                    ldsm4(r, boff + brow * ROWB + bchk * 16);
                    bfr[2 * bn][0] = r[0]; bfr[2 * bn][1] = r[1];
                    bfr[2 * bn + 1][0] = r[2]; bfr[2 * bn + 1][1] = r[3];
                }
#pragma unroll
                for (int fm = 0; fm < 4; fm++) {
                    uint32_t a[4];
                    int arow = warp_m * 64 + fm * 16 + arow_l;
                    ldsm4(a, aoff + arow * ROWB + achk * 16);
#pragma unroll
                    for (int fn = 0; fn < 6; fn++)
                        mma16816(acc[fm][fn], a, bfr[fn]);
                }
            }
        }
        if (c + 1 < NKC) {
            STCHUNK((c + 1) & 1);
            __syncthreads();
            if (c + 2 < NKC) LDCHUNK(c + 2);
        }
    }

    const int g = lane >> 2;
    const int t = lane & 3;
#pragma unroll
    for (int fn = 0; fn < 6; fn++) {
        const int nblk = warp_n * 48 + fn * 8;
        const int n    = nblk + 2 * t;
#pragma unroll
        for (int fm = 0; fm < 4; fm++) {
#pragma unroll
            for (int half = 0; half < 2; half++) {
                const int m = m0 + warp_m * 64 + fm * 16 + g + half * 8;
                float v0 = acc[fm][fn][2 * half + 0];
                float v1 = acc[fm][fn][2 * half + 1];
                if (nblk < 64) {
                    v0 = softplus_f(v0 + bd[n]);
                    v1 = softplus_f(v1 + bd[n + 1]);
                    *(float2*)&g_delta[(size_t)m * NS + n] = make_float2(v0, v1);
                } else if (nblk < 128) {
                    const int j = n - 64;
                    float2 xv = *(const float2*)&x[(size_t)m * DM + j];
                    v0 = (v0 + bb[j]) * xv.x;
                    v1 = (v1 + bb[j + 1]) * xv.y;
                    *(float2*)&g_u[(size_t)m * NS + j] = make_float2(v0, v1);
                } else {
                    const int j = n - 128;
                    v0 += bc[j];
                    v1 += bc[j + 1];
                    *(float2*)&g_c[(size_t)m * NS + j] = make_float2(v0, v1);
                }
            }
        }
    }
}

// ------------------------------- scan pass 1 (fine) -------------------------
// grid 512 (b[8] x fine-chunk[32] x half[2]), 256 thr = 8 warps x 4 i-rows.
// lane: isub = l>>3, g = l&7 owns j in {4g..4g+3, 32+4g..32+4g+3}.
__global__ void __launch_bounds__(256, 4)
scan1_kernel(const float* __restrict__ A_log) {
    __shared__ float su[2][TS][NS];
    __shared__ float sd[2][TS][NS];

    const int tid = threadIdx.x;
    const int w   = tid >> 5;
    const int l   = tid & 31;
    const int isub = l >> 3;
    const int g    = l & 7;
    const int bx  = blockIdx.x;
    const int b     = bx >> 6;
    const int chunk = (bx >> 1) & 31;       // fine chunk
    const int half  = bx & 1;
    const int i     = half * 32 + w * 4 + isub;
    const int row   = b * NS + i;
    const int t0    = chunk * LQF;

    float a[8];
    *(float4*)&a[0] = *(const float4*)&A_log[i * NS + 4 * g];
    *(float4*)&a[4] = *(const float4*)&A_log[i * NS + 32 + 4 * g];
#pragma unroll
    for (int k = 0; k < 8; k++) a[k] *= LOG2E;

    const float* ubase = g_u + ((size_t)(b * SQ + t0)) * NS;
    const float* dbase = g_delta + ((size_t)(b * SQ + t0)) * NS;

    const int ss = tid >> 4, sp = (tid & 15) << 2;

    float4 ru = *(const float4*)(ubase + (size_t)ss * NS + sp);
    float4 rd = *(const float4*)(dbase + (size_t)ss * NS + sp);
    *(float4*)&su[0][ss][sp] = ru;
    *(float4*)&sd[0][ss][sp] = rd;
    __syncthreads();

    float h[8];
#pragma unroll
    for (int k = 0; k < 8; k++) h[k] = 0.0f;
    float dsum = 0.0f;

    for (int tile = 0; tile < NTILF; tile++) {
        const int cur = tile & 1;
        if (tile + 1 < NTILF) {
            const int toff = (tile + 1) * TS;
            ru = *(const float4*)(ubase + (size_t)(toff + ss) * NS + sp);
            rd = *(const float4*)(dbase + (size_t)(toff + ss) * NS + sp);
        }
#pragma unroll
        for (int s = 0; s < TS; s++) {
            float d = sd[cur][s][i];
            dsum += d;
            float4 ua = *(const float4*)&su[cur][s][4 * g];
            float4 ub = *(const float4*)&su[cur][s][32 + 4 * g];
            h[0] = ex2(a[0] * d) * h[0] + ua.x;
            h[1] = ex2(a[1] * d) * h[1] + ua.y;
            h[2] = ex2(a[2] * d) * h[2] + ua.z;
            h[3] = ex2(a[3] * d) * h[3] + ua.w;
            h[4] = ex2(a[4] * d) * h[4] + ub.x;
            h[5] = ex2(a[5] * d) * h[5] + ub.y;
            h[6] = ex2(a[6] * d) * h[6] + ub.z;
            h[7] = ex2(a[7] * d) * h[7] + ub.w;
        }
        if (tile + 1 < NTILF) {
            const int nxt = cur ^ 1;
            *(float4*)&su[nxt][ss][sp] = ru;
            *(float4*)&sd[nxt][ss][sp] = rd;
            __syncthreads();
        }
    }

    float* he = g_hend + ((size_t)row * GQF + chunk) * NS;
    *(float4*)(he + 4 * g)      = make_float4(h[0], h[1], h[2], h[3]);
    *(float4*)(he + 32 + 4 * g) = make_float4(h[4], h[5], h[6], h[7]);
    if (g == 0) g_dsum[row * GQF + chunk] = dsum;
}

// ------------------------------- scan pass 3 --------------------------------
// grid 256 (b[8] x coarse chunk[16] x half[2]); lookback over FINE entries.
__global__ void __launch_bounds__(256, 1)
scan3_kernel(const float* __restrict__ A_log, float* __restrict__ out) {
    __shared__ float su[2][TS][NS];
    __shared__ float sc[2][TS][NS];
    __shared__ float sd[2][TS][NS];
    __shared__ float ys[2][TS][32];

    const int tid = threadIdx.x;
    const int w   = tid >> 5;
    const int l   = tid & 31;
    const int isub = l >> 3;
    const int g    = l & 7;
    const int bx  = blockIdx.x;
    const int b     = bx >> 5;
    const int chunk = (bx >> 1) & 15;       // coarse chunk
    const int half  = bx & 1;
    const int iblk  = w * 4 + isub;          // 0..31
    const int i     = half * 32 + iblk;
    const int row   = b * NS + i;
    const int t0    = chunk * LQ;

    float a[8];
    *(float4*)&a[0] = *(const float4*)&A_log[i * NS + 4 * g];
    *(float4*)&a[4] = *(const float4*)&A_log[i * NS + 32 + 4 * g];
#pragma unroll
    for (int k = 0; k < 8; k++) a[k] *= LOG2E;

    const float* ubase = g_u + ((size_t)(b * SQ + t0)) * NS;
    const float* cbase = g_c + ((size_t)(b * SQ + t0)) * NS;
    const float* dbase = g_delta + ((size_t)(b * SQ + t0)) * NS;

    const int ss = tid >> 4, sp = (tid & 15) << 2;

    // stage tile 0 (hides lookback behind LDGs)
    float4 ru = *(const float4*)(ubase + (size_t)ss * NS + sp);
    float4 rc = *(const float4*)(cbase + (size_t)ss * NS + sp);
    float4 rd = *(const float4*)(dbase + (size_t)ss * NS + sp);
    *(float4*)&su[0][ss][sp] = ru;
    *(float4*)&sc[0][ss][sp] = rc;
    *(float4*)&sd[0][ss][sp] = rd;

    // ---- lookback over fine chunks p < 2*chunk ----
    float h[8];
#pragma unroll
    for (int k = 0; k < 8; k++) h[k] = 0.0f;
    {
        float S = 0.0f;
        const float* dsp = g_dsum + row * GQF;
        const float* hep = g_hend + ((size_t)row * GQF) * NS;
        for (int p = 2 * chunk - 1; p >= 0; p--) {
            float4 he0 = *(const float4*)(hep + (size_t)p * NS + 4 * g);
            float4 he1 = *(const float4*)(hep + (size_t)p * NS + 32 + 4 * g);
            h[0] += ex2(a[0] * S) * he0.x;
            h[1] += ex2(a[1] * S) * he0.y;
            h[2] += ex2(a[2] * S) * he0.z;
            h[3] += ex2(a[3] * S) * he0.w;
            h[4] += ex2(a[4] * S) * he1.x;
            h[5] += ex2(a[5] * S) * he1.y;
            h[6] += ex2(a[6] * S) * he1.z;
            h[7] += ex2(a[7] * S) * he1.w;
            S += dsp[p];
        }
    }
    __syncthreads();

    for (int tile = 0; tile < NTIL; tile++) {
        const int cur = tile & 1;
        if (tile + 1 < NTIL) {
            const int toff = (tile + 1) * TS;
            ru = *(const float4*)(ubase + (size_t)(toff + ss) * NS + sp);
            rc = *(const float4*)(cbase + (size_t)(toff + ss) * NS + sp);
            rd = *(const float4*)(dbase + (size_t)(toff + ss) * NS + sp);
        }
#pragma unroll
        for (int s = 0; s < TS; s++) {
            float d = sd[cur][s][i];
            float4 ua = *(const float4*)&su[cur][s][4 * g];
            float4 ub = *(const float4*)&su[cur][s][32 + 4 * g];
            float4 ca = *(const float4*)&sc[cur][s][4 * g];
            float4 cb = *(const float4*)&sc[cur][s][32 + 4 * g];
            h[0] = ex2(a[0] * d) * h[0] + ua.x;
            h[1] = ex2(a[1] * d) * h[1] + ua.y;
            h[2] = ex2(a[2] * d) * h[2] + ua.z;
            h[3] = ex2(a[3] * d) * h[3] + ua.w;
            h[4] = ex2(a[4] * d) * h[4] + ub.x;
            h[5] = ex2(a[5] * d) * h[5] + ub.y;
            h[6] = ex2(a[6] * d) * h[6] + ub.z;
            h[7] = ex2(a[7] * d) * h[7] + ub.w;
            float p = ca.x * h[0] + ca.y * h[1] + ca.z * h[2] + ca.w * h[3]
                    + cb.x * h[4] + cb.y * h[5] + cb.z * h[6] + cb.w * h[7];
            p += __shfl_xor_sync(0xffffffffu, p, 4);
            p += __shfl_xor_sync(0xffffffffu, p, 2);
            p += __shfl_xor_sync(0xffffffffu, p, 1);
            if (g == 0) ys[cur][s][iblk] = p;
        }
        if (tile + 1 < NTIL) {
            const int nxt = cur ^ 1;
            *(float4*)&su[nxt][ss][sp] = ru;
            *(float4*)&sc[nxt][ss][sp] = rc;
            *(float4*)&sd[nxt][ss][sp] = rd;
        }
        __syncthreads();
        // coalesced y writeout for this tile
        {
            const int yt = tid >> 4;            // 0..15
            const int yi = (tid & 15) << 1;     // 0..30
            float2 yv = *(const float2*)&ys[cur][yt][yi];
            const int t = t0 + tile * TS + yt;
            *(float2*)&out[((size_t)(b * SQ + t)) * NS + half * 32 + yi] = yv;
        }
    }
}

// --------------------------------- launch -----------------------------------
extern "C" void kernel_launch(void* const* d_in, const int* in_sizes, int n_in,
                              void* d_out, int out_size) {
    const float* x  = (const float*)d_in[0];
    const float* Wd = (const float*)d_in[7];
    const float* bd = (const float*)d_in[8];
    const float* Wb = (const float*)d_in[9];
    const float* bb = (const float*)d_in[10];
    const float* Wc = (const float*)d_in[11];
    const float* bc = (const float*)d_in[12];
    const float* A  = (const float*)d_in[13];
    float* out = (float*)d_out;

    cudaFuncSetAttribute(proj_mma_kernel,
                         cudaFuncAttributeMaxDynamicSharedMemorySize, SMEM_MMA);

    wconv_kernel<<<NTOT * DM / 8 / 256, 256>>>(Wd, Wb, Wc);
    proj_mma_kernel<<<ROWS / MT, 256, SMEM_MMA>>>(x, bd, bb, bc);
    scan1_kernel<<<BQ * GQF * 2, 256>>>(A);
    scan3_kernel<<<BQ * GQ * 2, 256>>>(A, out);
}

// round 16
// speedup vs baseline: 1.1444x; 1.0105x over previous
#include <cuda_runtime.h>
#include <cuda_bf16.h>
#include <math.h>
#include <cstdint>

// ---------------------------------------------------------------------------
// SelectiveStateSpace: B=8, S=2048, D_MODEL=1024, N=64
//   wconv    : W[192,1024] fp32 -> bf16 hi/lo split
//   proj_mma : ldmatrix + mma.sync bf16 3-term GEMM  D = X @ Wcat^T
//   scan1    : 64-step chunks, whole-chunk smem, local scan -> h_end, sum(d)
//   scan3    : 64-step chunks, lookback -> h_start, rescan, emit y
// R16: both scans grid 512 @ 4 blocks/SM (launch_bounds(256,4)) = single wave
// at 6.9 warps/SMSP; single-buffer whole-chunk staging to fit 64 regs.
// ---------------------------------------------------------------------------

#define BQ   8
#define SQ   2048
#define DM   1024
#define NS   64
#define ROWS (BQ * SQ)        // 16384
#define RQ   (BQ * NS)        // 512
#define GQF  32               // chunks per row
#define LQF  (SQ / GQF)       // 64 steps per chunk

#define MT   128
#define NTOT 192
#define KC   32
#define NKC  (DM / KC)        // 32

#define LOG2E 1.4426950408889634f

// proj smem geometry (bytes): rows padded to 80B for ldmatrix
#define ROWB   80
#define A_TERM (MT * ROWB)
#define B_TERM (NTOT * ROWB)
#define A_OFF  0
#define B_OFF  (2 * A_TERM)
#define STG_SZ (2 * A_TERM + 2 * B_TERM)
#define SMEM_MMA (2 * STG_SZ)

// scan3 dynamic smem layout (floats)
#define S3_SU 0
#define S3_SC 4096
#define S3_SD 8192
#define S3_YS 10240
#define SMEM_S3 (12288 * 4)    // 49152 B

// scratch (device globals; no allocation allowed)
__device__ float g_delta[ROWS * NS];
__device__ float g_u[ROWS * NS];
__device__ float g_c[ROWS * NS];
__device__ float g_hend[RQ * GQF * NS];
__device__ float g_dsum[RQ * GQF];
__device__ uint4 g_Whi4[NTOT * DM / 8];
__device__ uint4 g_Wlo4[NTOT * DM / 8];

// ------------------------------ helpers -------------------------------------
__device__ __forceinline__ uint32_t smem_u32(const void* p) {
    uint32_t a;
    asm("{ .reg .u64 t; cvta.to.shared.u64 t, %1; cvt.u32.u64 %0, t; }"
        : "=r"(a) : "l"(p));
    return a;
}
__device__ __forceinline__ float ex2(float x) {
    float r;
    asm("ex2.approx.ftz.f32 %0, %1;" : "=f"(r) : "f"(x));
    return r;
}
__device__ __forceinline__ float softplus_f(float v) {
    return (v > 20.0f) ? v : log1pf(expf(v));
}
__device__ __forceinline__ uint32_t hipack(float a, float b) {
    __nv_bfloat162 h;
    h.x = __float2bfloat16(a);
    h.y = __float2bfloat16(b);
    return *(uint32_t*)&h;
}
__device__ __forceinline__ uint32_t lopack(float a, float b) {
    __nv_bfloat16 ha = __float2bfloat16(a), hb = __float2bfloat16(b);
    __nv_bfloat162 h;
    h.x = __float2bfloat16(a - __bfloat162float(ha));
    h.y = __float2bfloat16(b - __bfloat162float(hb));
    return *(uint32_t*)&h;
}
__device__ __forceinline__ void ldsm4(uint32_t* r, uint32_t addr) {
    asm volatile("ldmatrix.sync.aligned.m8n8.x4.shared.b16 {%0,%1,%2,%3}, [%4];"
                 : "=r"(r[0]), "=r"(r[1]), "=r"(r[2]), "=r"(r[3]) : "r"(addr));
}
__device__ __forceinline__ void mma16816(float* c, const uint32_t* a, const uint32_t* b) {
    asm volatile(
        "mma.sync.aligned.m16n8k16.row.col.f32.bf16.bf16.f32 "
        "{%0,%1,%2,%3}, {%4,%5,%6,%7}, {%8,%9}, {%0,%1,%2,%3};"
        : "+f"(c[0]), "+f"(c[1]), "+f"(c[2]), "+f"(c[3])
        : "r"(a[0]), "r"(a[1]), "r"(a[2]), "r"(a[3]), "r"(b[0]), "r"(b[1]));
}

// ------------------------------ W conversion --------------------------------
__global__ void __launch_bounds__(256, 1)
wconv_kernel(const float* __restrict__ Wd, const float* __restrict__ Wb,
             const float* __restrict__ Wc) {
    int gi = blockIdx.x * 256 + threadIdx.x;
    int row = gi >> 7;
    int k8  = (gi & 127) * 8;
    const float* src = (row < 64) ? (Wd + (size_t)row * DM)
                    : (row < 128) ? (Wb + (size_t)(row - 64) * DM)
                                  : (Wc + (size_t)(row - 128) * DM);
    float f[8];
    *(float4*)&f[0] = *(const float4*)(src + k8);
    *(float4*)&f[4] = *(const float4*)(src + k8 + 4);
    uint4 hi, lo;
    hi.x = hipack(f[0], f[1]); hi.y = hipack(f[2], f[3]);
    hi.z = hipack(f[4], f[5]); hi.w = hipack(f[6], f[7]);
    lo.x = lopack(f[0], f[1]); lo.y = lopack(f[2], f[3]);
    lo.z = lopack(f[4], f[5]); lo.w = lopack(f[6], f[7]);
    g_Whi4[gi] = hi;
    g_Wlo4[gi] = lo;
}

// ------------------------------ proj (mma.sync) -----------------------------
__global__ void __launch_bounds__(256, 1)
proj_mma_kernel(const float* __restrict__ x,
                const float* __restrict__ bd, const float* __restrict__ bb,
                const float* __restrict__ bc) {
    extern __shared__ char smem[];
    const uint32_t sb = smem_u32(smem);
    const int tid    = threadIdx.x;
    const int lane   = tid & 31;
    const int warp   = tid >> 5;
    const int warp_m = warp >> 2;
    const int warp_n = warp & 3;
    const int m0     = blockIdx.x * MT;

    float acc[4][6][4];
#pragma unroll
    for (int fm = 0; fm < 4; fm++)
#pragma unroll
        for (int fn = 0; fn < 6; fn++)
#pragma unroll
            for (int e = 0; e < 4; e++) acc[fm][fn][e] = 0.0f;

    float4 xr[4];
    uint4  wh[3], wl[3];
    const int xrow = tid >> 1;
    const int xco  = (tid & 1) * 16;

#define LDCHUNK(c)                                                              \
    do {                                                                        \
        const float* xp = x + (size_t)(m0 + xrow) * DM + (c) * KC + xco;        \
        xr[0] = *(const float4*)(xp + 0);                                       \
        xr[1] = *(const float4*)(xp + 4);                                       \
        xr[2] = *(const float4*)(xp + 8);                                       \
        xr[3] = *(const float4*)(xp + 12);                                      \
        _Pragma("unroll")                                                       \
        for (int q = 0; q < 3; q++) {                                           \
            int idx = tid + q * 256;                                            \
            int wrow = idx >> 2, wch = idx & 3;                                 \
            int u4 = wrow * 128 + (c) * 4 + wch;                                \
            wh[q] = g_Whi4[u4];                                                 \
            wl[q] = g_Wlo4[u4];                                                 \
        }                                                                       \
    } while (0)

#define STCHUNK(buf)                                                            \
    do {                                                                        \
        char* bs = smem + (buf) * STG_SZ;                                       \
        uint4 h0 = make_uint4(hipack(xr[0].x, xr[0].y), hipack(xr[0].z, xr[0].w),\
                              hipack(xr[1].x, xr[1].y), hipack(xr[1].z, xr[1].w));\
        uint4 h1 = make_uint4(hipack(xr[2].x, xr[2].y), hipack(xr[2].z, xr[2].w),\
                              hipack(xr[3].x, xr[3].y), hipack(xr[3].z, xr[3].w));\
        uint4 l0 = make_uint4(lopack(xr[0].x, xr[0].y), lopack(xr[0].z, xr[0].w),\
                              lopack(xr[1].x, xr[1].y), lopack(xr[1].z, xr[1].w));\
        uint4 l1 = make_uint4(lopack(xr[2].x, xr[2].y), lopack(xr[2].z, xr[2].w),\
                              lopack(xr[3].x, xr[3].y), lopack(xr[3].z, xr[3].w));\
        int ach = (tid & 1) * 2;                                                \
        *(uint4*)(bs + A_OFF + xrow * ROWB + ach * 16)        = h0;             \
        *(uint4*)(bs + A_OFF + xrow * ROWB + (ach + 1) * 16)  = h1;             \
        *(uint4*)(bs + A_OFF + A_TERM + xrow * ROWB + ach * 16)       = l0;     \
        *(uint4*)(bs + A_OFF + A_TERM + xrow * ROWB + (ach + 1) * 16) = l1;     \
        _Pragma("unroll")                                                       \
        for (int q = 0; q < 3; q++) {                                           \
            int idx = tid + q * 256;                                            \
            int wrow = idx >> 2, wch = idx & 3;                                 \
            *(uint4*)(bs + B_OFF + wrow * ROWB + wch * 16) = wh[q];             \
            *(uint4*)(bs + B_OFF + B_TERM + wrow * ROWB + wch * 16) = wl[q];    \
        }                                                                       \
    } while (0)

    LDCHUNK(0);
    STCHUNK(0);
    __syncthreads();
    LDCHUNK(1);

    for (int c = 0; c < NKC; c++) {
        const uint32_t bs = sb + (uint32_t)(c & 1) * STG_SZ;
#pragma unroll
        for (int ks = 0; ks < 2; ks++) {
            const int arow_l = (lane & 15);
            const int achk   = ks * 2 + (lane >> 4);
            const int brow_l = (lane & 7) + ((lane >> 4) << 3);
            const int bchk   = ks * 2 + ((lane >> 3) & 1);
#pragma unroll
            for (int term = 0; term < 3; term++) {
                const uint32_t aoff = bs + A_OFF + ((term == 2) ? A_TERM : 0);
                const uint32_t boff = bs + B_OFF + ((term == 1) ? B_TERM : 0);
                uint32_t bfr[6][2];
#pragma unroll
                for (int bn = 0; bn < 3; bn++) {
                    uint32_t r[4];
                    int brow = warp_n * 48 + bn * 16 + brow_l;
                    ldsm4(r, boff + brow * ROWB + bchk * 16);
                    bfr[2 * bn][0] = r[0]; bfr[2 * bn][1] = r[1];
                    bfr[2 * bn + 1][0] = r[2]; bfr[2 * bn + 1][1] = r[3];
                }
#pragma unroll
                for (int fm = 0; fm < 4; fm++) {
                    uint32_t a[4];
                    int arow = warp_m * 64 + fm * 16 + arow_l;
                    ldsm4(a, aoff + arow * ROWB + achk * 16);
#pragma unroll
                    for (int fn = 0; fn < 6; fn++)
                        mma16816(acc[fm][fn], a, bfr[fn]);
                }
            }
        }
        if (c + 1 < NKC) {
            STCHUNK((c + 1) & 1);
            __syncthreads();
            if (c + 2 < NKC) LDCHUNK(c + 2);
        }
    }

    const int g = lane >> 2;
    const int t = lane & 3;
#pragma unroll
    for (int fn = 0; fn < 6; fn++) {
        const int nblk = warp_n * 48 + fn * 8;
        const int n    = nblk + 2 * t;
#pragma unroll
        for (int fm = 0; fm < 4; fm++) {
#pragma unroll
            for (int half = 0; half < 2; half++) {
                const int m = m0 + warp_m * 64 + fm * 16 + g + half * 8;
                float v0 = acc[fm][fn][2 * half + 0];
                float v1 = acc[fm][fn][2 * half + 1];
                if (nblk < 64) {
                    v0 = softplus_f(v0 + bd[n]);
                    v1 = softplus_f(v1 + bd[n + 1]);
                    *(float2*)&g_delta[(size_t)m * NS + n] = make_float2(v0, v1);
                } else if (nblk < 128) {
                    const int j = n - 64;
                    float2 xv = *(const float2*)&x[(size_t)m * DM + j];
                    v0 = (v0 + bb[j]) * xv.x;
                    v1 = (v1 + bb[j + 1]) * xv.y;
                    *(float2*)&g_u[(size_t)m * NS + j] = make_float2(v0, v1);
                } else {
                    const int j = n - 128;
                    v0 += bc[j];
                    v1 += bc[j + 1];
                    *(float2*)&g_c[(size_t)m * NS + j] = make_float2(v0, v1);
                }
            }
        }
    }
}

// ------------------------------- scan pass 1 --------------------------------
// grid 512 (b[8] x chunk[32] x half[2]), 256 thr = 8 warps x 4 i-rows,
// 4 blocks/SM. Whole 64-step chunk staged once; single sync.
__global__ void __launch_bounds__(256, 4)
scan1_kernel(const float* __restrict__ A_log) {
    __shared__ float su[LQF * NS];      // 16 KB
    __shared__ float sd[LQF * 32];      // 8 KB (this half's i rows)

    const int tid = threadIdx.x;
    const int w   = tid >> 5;
    const int l   = tid & 31;
    const int isub = l >> 3;
    const int g    = l & 7;
    const int bx  = blockIdx.x;
    const int b     = bx >> 6;
    const int chunk = (bx >> 1) & 31;
    const int half  = bx & 1;
    const int iblk  = w * 4 + isub;      // 0..31
    const int i     = half * 32 + iblk;
    const int row   = b * NS + i;
    const int t0    = chunk * LQF;

    float a[8];
    *(float4*)&a[0] = *(const float4*)&A_log[i * NS + 4 * g];
    *(float4*)&a[4] = *(const float4*)&A_log[i * NS + 32 + 4 * g];
#pragma unroll
    for (int k = 0; k < 8; k++) a[k] *= LOG2E;

    const float* ubase = g_u + ((size_t)(b * SQ + t0)) * NS;
    const float* dbase = g_delta + ((size_t)(b * SQ + t0)) * NS + half * 32;

    // stage u: 1024 f4 -> 4/thread; d: 512 f4 -> 2/thread
#pragma unroll
    for (int k = 0; k < 4; k++) {
        int idx = tid + k * 256;
        int r = idx >> 4, c4 = (idx & 15) << 2;
        *(float4*)&su[r * 64 + c4] = *(const float4*)(ubase + (size_t)r * NS + c4);
    }
#pragma unroll
    for (int k = 0; k < 2; k++) {
        int idx = tid + k * 256;
        int r = idx >> 3, c4 = (idx & 7) << 2;
        *(float4*)&sd[r * 32 + c4] = *(const float4*)(dbase + (size_t)r * NS + c4);
    }
    __syncthreads();

    float h[8] = {0.f, 0.f, 0.f, 0.f, 0.f, 0.f, 0.f, 0.f};
    float dsum = 0.0f;

#pragma unroll 8
    for (int s = 0; s < LQF; s++) {
        float d = sd[s * 32 + iblk];
        float4 ua = *(const float4*)&su[s * 64 + 4 * g];
        float4 ub = *(const float4*)&su[s * 64 + 32 + 4 * g];
        dsum += d;
        h[0] = ex2(a[0] * d) * h[0] + ua.x;
        h[1] = ex2(a[1] * d) * h[1] + ua.y;
        h[2] = ex2(a[2] * d) * h[2] + ua.z;
        h[3] = ex2(a[3] * d) * h[3] + ua.w;
        h[4] = ex2(a[4] * d) * h[4] + ub.x;
        h[5] = ex2(a[5] * d) * h[5] + ub.y;
        h[6] = ex2(a[6] * d) * h[6] + ub.z;
        h[7] = ex2(a[7] * d) * h[7] + ub.w;
    }

    float* he = g_hend + ((size_t)row * GQF + chunk) * NS;
    *(float4*)(he + 4 * g)      = make_float4(h[0], h[1], h[2], h[3]);
    *(float4*)(he + 32 + 4 * g) = make_float4(h[4], h[5], h[6], h[7]);
    if (g == 0) g_dsum[row * GQF + chunk] = dsum;
}

// ------------------------------- scan pass 3 --------------------------------
// grid 512, 4 blocks/SM; lookback over fine entries p < chunk; whole chunk
// staged once (dynamic smem 48 KB).
__global__ void __launch_bounds__(256, 4)
scan3_kernel(const float* __restrict__ A_log, float* __restrict__ out) {
    extern __shared__ float sf[];
    float* su = sf + S3_SU;    // [64][64]
    float* sc = sf + S3_SC;    // [64][64]
    float* sd = sf + S3_SD;    // [64][32]
    float* ys = sf + S3_YS;    // [64][32]

    const int tid = threadIdx.x;
    const int w   = tid >> 5;
    const int l   = tid & 31;
    const int isub = l >> 3;
    const int g    = l & 7;
    const int bx  = blockIdx.x;
    const int b     = bx >> 6;
    const int chunk = (bx >> 1) & 31;
    const int half  = bx & 1;
    const int iblk  = w * 4 + isub;      // 0..31
    const int i     = half * 32 + iblk;
    const int row   = b * NS + i;
    const int t0    = chunk * LQF;

    float a[8];
    *(float4*)&a[0] = *(const float4*)&A_log[i * NS + 4 * g];
    *(float4*)&a[4] = *(const float4*)&A_log[i * NS + 32 + 4 * g];
#pragma unroll
    for (int k = 0; k < 8; k++) a[k] *= LOG2E;

    const float* ubase = g_u + ((size_t)(b * SQ + t0)) * NS;
    const float* cbase = g_c + ((size_t)(b * SQ + t0)) * NS;
    const float* dbase = g_delta + ((size_t)(b * SQ + t0)) * NS + half * 32;

    // stage u,c: 4 f4/thread each; d: 2 f4/thread
#pragma unroll
    for (int k = 0; k < 4; k++) {
        int idx = tid + k * 256;
        int r = idx >> 4, c4 = (idx & 15) << 2;
        *(float4*)&su[r * 64 + c4] = *(const float4*)(ubase + (size_t)r * NS + c4);
        *(float4*)&sc[r * 64 + c4] = *(const float4*)(cbase + (size_t)r * NS + c4);
    }
#pragma unroll
    for (int k = 0; k < 2; k++) {
        int idx = tid + k * 256;
        int r = idx >> 3, c4 = (idx & 7) << 2;
        *(float4*)&sd[r * 32 + c4] = *(const float4*)(dbase + (size_t)r * NS + c4);
    }

    // ---- lookback (gmem-only; overlaps staging latency) ----
    float h[8] = {0.f, 0.f, 0.f, 0.f, 0.f, 0.f, 0.f, 0.f};
    {
        float S = 0.0f;
        const float* dsp = g_dsum + row * GQF;
        const float* hep = g_hend + ((size_t)row * GQF) * NS;
        for (int p = chunk - 1; p >= 0; p--) {
            float4 he0 = *(const float4*)(hep + (size_t)p * NS + 4 * g);
            float4 he1 = *(const float4*)(hep + (size_t)p * NS + 32 + 4 * g);
            h[0] += ex2(a[0] * S) * he0.x;
            h[1] += ex2(a[1] * S) * he0.y;
            h[2] += ex2(a[2] * S) * he0.z;
            h[3] += ex2(a[3] * S) * he0.w;
            h[4] += ex2(a[4] * S) * he1.x;
            h[5] += ex2(a[5] * S) * he1.y;
            h[6] += ex2(a[6] * S) * he1.z;
            h[7] += ex2(a[7] * S) * he1.w;
            S += dsp[p];
        }
    }
    __syncthreads();

    // ---- rescan with h_start, emit y ----
#pragma unroll 8
    for (int s = 0; s < LQF; s++) {
        float d = sd[s * 32 + iblk];
        float4 ua = *(const float4*)&su[s * 64 + 4 * g];
        float4 ub = *(const float4*)&su[s * 64 + 32 + 4 * g];
        float4 ca = *(const float4*)&sc[s * 64 + 4 * g];
        float4 cb = *(const float4*)&sc[s * 64 + 32 + 4 * g];
        h[0] = ex2(a[0] * d) * h[0] + ua.x;
        h[1] = ex2(a[1] * d) * h[1] + ua.y;
        h[2] = ex2(a[2] * d) * h[2] + ua.z;
        h[3] = ex2(a[3] * d) * h[3] + ua.w;
        h[4] = ex2(a[4] * d) * h[4] + ub.x;
        h[5] = ex2(a[5] * d) * h[5] + ub.y;
        h[6] = ex2(a[6] * d) * h[6] + ub.z;
        h[7] = ex2(a[7] * d) * h[7] + ub.w;
        float p = ca.x * h[0] + ca.y * h[1] + ca.z * h[2] + ca.w * h[3]
                + cb.x * h[4] + cb.y * h[5] + cb.z * h[6] + cb.w * h[7];
        p += __shfl_xor_sync(0xffffffffu, p, 4);
        p += __shfl_xor_sync(0xffffffffu, p, 2);
        p += __shfl_xor_sync(0xffffffffu, p, 1);
        if (g == 0) ys[s * 32 + iblk] = p;
    }
    __syncthreads();

    // ---- coalesced y writeout: 512 f4 -> 2 f4/thread ----
#pragma unroll
    for (int k = 0; k < 2; k++) {
        int idx = tid + k * 256;
        int s = idx >> 3, c4 = (idx & 7) << 2;
        *(float4*)&out[((size_t)(b * SQ + t0 + s)) * NS + half * 32 + c4] =
            *(const float4*)&ys[s * 32 + c4];
    }
}

// --------------------------------- launch -----------------------------------
extern "C" void kernel_launch(void* const* d_in, const int* in_sizes, int n_in,
                              void* d_out, int out_size) {
    const float* x  = (const float*)d_in[0];
    const float* Wd = (const float*)d_in[7];
    const float* bd = (const float*)d_in[8];
    const float* Wb = (const float*)d_in[9];
    const float* bb = (const float*)d_in[10];
    const float* Wc = (const float*)d_in[11];
    const float* bc = (const float*)d_in[12];
    const float* A  = (const float*)d_in[13];
    float* out = (float*)d_out;

    cudaFuncSetAttribute(proj_mma_kernel,
                         cudaFuncAttributeMaxDynamicSharedMemorySize, SMEM_MMA);
    cudaFuncSetAttribute(scan3_kernel,
                         cudaFuncAttributeMaxDynamicSharedMemorySize, SMEM_S3);

    wconv_kernel<<<NTOT * DM / 8 / 256, 256>>>(Wd, Wb, Wc);
    proj_mma_kernel<<<ROWS / MT, 256, SMEM_MMA>>>(x, bd, bb, bc);
    scan1_kernel<<<BQ * GQF * 2, 256>>>(A);
    scan3_kernel<<<BQ * GQF * 2, 256, SMEM_S3>>>(A, out);
}